// round 4
// baseline (speedup 1.0000x reference)
#include <cuda_runtime.h>
#include <math.h>

// Problem dims
#define BB 4
#define MM 2048
#define NN 2048
#define DD 256
#define D2 512
#define LN_EPS 1e-5f
#define TH_VAL 0.1f
#define NEG_HUGE -3.0e38f

// ---------------- scratch ----------------
#define SZP (4LL*2048*2048)   // 16,777,216
#define SZV (4LL*2048*256)    //  2,097,152
#define SZH (4LL*2048*512)    //  4,194,304
#define SZS (8192LL)

constexpr size_t O_P01 = 0;
constexpr size_t O_P10 = O_P01 + SZP;
constexpr size_t O_SIM = O_P10 + SZP;
constexpr size_t O_V0  = O_SIM + SZP;
constexpr size_t O_V1  = O_V0 + SZV;
constexpr size_t O_MP0 = O_V1 + SZV;
constexpr size_t O_MP1 = O_MP0 + SZV;
constexpr size_t O_M0  = O_MP1 + SZV;
constexpr size_t O_M1  = O_M0 + SZV;
constexpr size_t O_CC0 = O_M1 + SZV;
constexpr size_t O_CC1 = O_CC0 + SZH;
constexpr size_t O_H0  = O_CC1 + SZH;
constexpr size_t O_H1  = O_H0 + SZH;
constexpr size_t O_D0  = O_H1 + SZH;
constexpr size_t O_D1  = O_D0 + SZV;
constexpr size_t O_MD0 = O_D1 + SZV;
constexpr size_t O_MD1 = O_MD0 + SZV;
constexpr size_t O_RMAX = O_MD1 + SZV;
constexpr size_t O_RINV = O_RMAX + SZS;
constexpr size_t O_CMAX = O_RINV + SZS;
constexpr size_t O_CINV = O_CMAX + SZS;
constexpr size_t O_RLSE = O_CINV + SZS;
constexpr size_t O_CLSE = O_RLSE + SZS;
constexpr size_t O_Z0   = O_CLSE + SZS;
constexpr size_t O_Z1   = O_Z0 + SZS;
constexpr size_t O_RADJ = O_Z1 + SZS;
constexpr size_t O_CADJ = O_RADJ + SZS;
constexpr size_t O_BRD0 = O_CADJ + SZS;
constexpr size_t O_BRD1 = O_BRD0 + SZS;
constexpr size_t O_ROWV = O_BRD1 + SZS;
constexpr size_t O_COLV = O_ROWV + SZS;
constexpr size_t O_MS0  = O_COLV + SZS;
constexpr size_t O_TOTAL = O_MS0 + SZS;

__device__ float g_scratch[O_TOTAL];
__device__ int   g_iscratch[3 * 8192];   // rowj, colj, valid0

__device__ __forceinline__ float softplusf(float x) {
    return fmaxf(x, 0.f) + log1pf(expf(-fabsf(x)));
}

// ---------------- generic tiled GEMM: C = scale*(A * Bt^T + bias) + res ----------------
// A: [R,K] row-major. Bt: [N,K] row-major (i.e. B^T). Batched via blockIdx.z + strides.
#define GBM 128
#define GBN 128
#define GBK 16

__global__ __launch_bounds__(256) void gemm_tn_kernel(
    const float* __restrict__ A, const float* __restrict__ Bt,
    const float* __restrict__ bias, const float* __restrict__ res,
    float scale, float* __restrict__ C,
    int R, int N, int K,
    long sA, long sB, long sC, long sRes)
{
    int b = blockIdx.z;
    A += (long)b * sA; Bt += (long)b * sB; C += (long)b * sC;
    if (res) res += (long)b * sRes;
    int bm = blockIdx.y * GBM;
    int bn = blockIdx.x * GBN;
    __shared__ float As[GBK][GBM];
    __shared__ float Bs[GBK][GBN];
    int tid = threadIdx.x;
    int tx = tid & 15, ty = tid >> 4;
    float acc[8][8];
    #pragma unroll
    for (int i = 0; i < 8; i++)
        #pragma unroll
        for (int j = 0; j < 8; j++) acc[i][j] = 0.f;

    int arow = tid >> 2;         // 0..63
    int ak = (tid & 3) * 4;      // 0,4,8,12

    for (int k0 = 0; k0 < K; k0 += GBK) {
        #pragma unroll
        for (int r = 0; r < 2; r++) {
            int row = arow + r * 64;
            float4 av = *(const float4*)(A + (long)(bm + row) * K + k0 + ak);
            As[ak+0][row] = av.x; As[ak+1][row] = av.y;
            As[ak+2][row] = av.z; As[ak+3][row] = av.w;
        }
        #pragma unroll
        for (int r = 0; r < 2; r++) {
            int col = arow + r * 64;
            float4 bv = *(const float4*)(Bt + (long)(bn + col) * K + k0 + ak);
            Bs[ak+0][col] = bv.x; Bs[ak+1][col] = bv.y;
            Bs[ak+2][col] = bv.z; Bs[ak+3][col] = bv.w;
        }
        __syncthreads();
        #pragma unroll
        for (int k = 0; k < GBK; k++) {
            float a[8], bb[8];
            #pragma unroll
            for (int i = 0; i < 8; i++) a[i] = As[k][ty*8 + i];
            #pragma unroll
            for (int j = 0; j < 8; j++) bb[j] = Bs[k][tx*8 + j];
            #pragma unroll
            for (int i = 0; i < 8; i++)
                #pragma unroll
                for (int j = 0; j < 8; j++)
                    acc[i][j] = fmaf(a[i], bb[j], acc[i][j]);
        }
        __syncthreads();
    }
    #pragma unroll
    for (int i = 0; i < 8; i++) {
        int row = bm + ty*8 + i;
        #pragma unroll
        for (int j = 0; j < 8; j++) {
            int col = bn + tx*8 + j;
            float v = acc[i][j];
            if (bias) v += bias[col];
            v *= scale;
            if (res) v += res[(long)row * N + col];
            C[(long)row * N + col] = v;
        }
    }
}

// B stored [K,N] row-major (normal GEMM). A: [R,K].
__global__ __launch_bounds__(256) void gemm_nn_kernel(
    const float* __restrict__ A, const float* __restrict__ B,
    const float* __restrict__ bias,
    float* __restrict__ C,
    int R, int N, int K,
    long sA, long sB, long sC)
{
    int b = blockIdx.z;
    A += (long)b * sA; B += (long)b * sB; C += (long)b * sC;
    int bm = blockIdx.y * GBM;
    int bn = blockIdx.x * GBN;
    __shared__ float As[GBK][GBM];
    __shared__ float Bs[GBK][GBN];
    int tid = threadIdx.x;
    int tx = tid & 15, ty = tid >> 4;
    float acc[8][8];
    #pragma unroll
    for (int i = 0; i < 8; i++)
        #pragma unroll
        for (int j = 0; j < 8; j++) acc[i][j] = 0.f;

    int arow = tid >> 2;
    int ak = (tid & 3) * 4;
    int krow = tid >> 5;         // 0..7
    int bc = (tid & 31) * 4;     // 0..124

    for (int k0 = 0; k0 < K; k0 += GBK) {
        #pragma unroll
        for (int r = 0; r < 2; r++) {
            int row = arow + r * 64;
            float4 av = *(const float4*)(A + (long)(bm + row) * K + k0 + ak);
            As[ak+0][row] = av.x; As[ak+1][row] = av.y;
            As[ak+2][row] = av.z; As[ak+3][row] = av.w;
        }
        #pragma unroll
        for (int r = 0; r < 2; r++) {
            int kk = krow + r * 8;
            float4 bv = *(const float4*)(B + (long)(k0 + kk) * N + bn + bc);
            *(float4*)&Bs[kk][bc] = bv;
        }
        __syncthreads();
        #pragma unroll
        for (int k = 0; k < GBK; k++) {
            float a[8], bb[8];
            #pragma unroll
            for (int i = 0; i < 8; i++) a[i] = As[k][ty*8 + i];
            #pragma unroll
            for (int j = 0; j < 8; j++) bb[j] = Bs[k][tx*8 + j];
            #pragma unroll
            for (int i = 0; i < 8; i++)
                #pragma unroll
                for (int j = 0; j < 8; j++)
                    acc[i][j] = fmaf(a[i], bb[j], acc[i][j]);
        }
        __syncthreads();
    }
    #pragma unroll
    for (int i = 0; i < 8; i++) {
        int row = bm + ty*8 + i;
        #pragma unroll
        for (int j = 0; j < 8; j++) {
            int col = bn + tx*8 + j;
            float v = acc[i][j];
            if (bias) v += bias[col];
            C[(long)row * N + col] = v;
        }
    }
}

// ---------------- reductions ----------------
// mode 0: out0=max, out1=1/sumexp ; mode 1: out0=lse
__global__ void reduce_rows_kernel(const float* __restrict__ X, int R, int C, int mode,
                                   float* __restrict__ out0, float* __restrict__ out1)
{
    int b = blockIdx.y, row = blockIdx.x, tid = threadIdx.x;
    const float* xr = X + (size_t)b * R * C + (size_t)row * C;
    __shared__ float sm[256];
    float mx = NEG_HUGE;
    for (int j = tid; j < C; j += 256) mx = fmaxf(mx, xr[j]);
    sm[tid] = mx; __syncthreads();
    for (int o = 128; o; o >>= 1) { if (tid < o) sm[tid] = fmaxf(sm[tid], sm[tid+o]); __syncthreads(); }
    mx = sm[0]; __syncthreads();
    float s = 0.f;
    for (int j = tid; j < C; j += 256) s += expf(xr[j] - mx);
    sm[tid] = s; __syncthreads();
    for (int o = 128; o; o >>= 1) { if (tid < o) sm[tid] += sm[tid+o]; __syncthreads(); }
    if (tid == 0) {
        int o = b * R + row;
        if (mode == 0) { out0[o] = mx; out1[o] = 1.f / sm[0]; }
        else out0[o] = mx + logf(sm[0]);
    }
}

__global__ void reduce_cols_kernel(const float* __restrict__ X, int R, int C, int mode,
                                   float* __restrict__ out0, float* __restrict__ out1)
{
    int b = blockIdx.y;
    int tid = threadIdx.x;
    int col = blockIdx.x * 32 + (tid & 31);
    int part = tid >> 5;
    const float* Xb = X + (size_t)b * R * C;
    float mx = NEG_HUGE, s = 0.f;
    for (int i = part; i < R; i += 8) {
        float a = Xb[(size_t)i * C + col];
        if (a > mx) { s = s * expf(mx - a) + 1.f; mx = a; }
        else s += expf(a - mx);
    }
    __shared__ float smx[256], ssum[256];
    smx[tid] = mx; ssum[tid] = s; __syncthreads();
    if (part == 0) {
        for (int p = 1; p < 8; p++) {
            float m2 = smx[p*32 + tid], s2 = ssum[p*32 + tid];
            if (m2 > mx) { s = s * expf(mx - m2) + s2; mx = m2; }
            else s += s2 * expf(m2 - mx);
        }
        int o = b * C + col;
        if (mode == 0) { out0[o] = mx; out1[o] = 1.f / s; }
        else out0[o] = mx + logf(s);
    }
}

// ---------------- softmax materialization: P01 (row softmax) + P10t (col softmax, transposed) ----
__global__ void build_P_kernel(const float* __restrict__ adj,
                               const float* __restrict__ rmax, const float* __restrict__ rinv,
                               const float* __restrict__ cmax, const float* __restrict__ cinv,
                               float* __restrict__ P01, float* __restrict__ P10t)
{
    int b = blockIdx.z;
    int tm = blockIdx.y * 32, tn = blockIdx.x * 32;
    __shared__ float s[32][33];
    const float* A = adj + (size_t)b * MM * NN;
    int tx = threadIdx.x, ty = threadIdx.y;
    #pragma unroll
    for (int i = 0; i < 4; i++) {
        int m = tm + ty + i * 8;
        float a = A[(size_t)m * NN + tn + tx];
        s[ty + i*8][tx] = a;
        P01[(size_t)b*MM*NN + (size_t)m*NN + tn + tx] = expf(a - rmax[b*MM + m]) * rinv[b*MM + m];
    }
    __syncthreads();
    #pragma unroll
    for (int i = 0; i < 4; i++) {
        int n = tn + ty + i * 8;
        int m = tm + tx;
        float a = s[tx][ty + i*8];
        P10t[(size_t)b*NN*MM + (size_t)n*MM + m] = expf(a - cmax[b*NN + n]) * cinv[b*NN + n];
    }
}

// ---------------- concat ----------------
__global__ void concat_kernel(const float* __restrict__ x, const float* __restrict__ m,
                              float* __restrict__ cc, int rows)
{
    int idx = blockIdx.x * blockDim.x + threadIdx.x;
    if (idx >= rows * 128) return;
    int row = idx >> 7, c4 = idx & 127;
    float4 v;
    if (c4 < 64) v = ((const float4*)x)[(size_t)row*64 + c4];
    else         v = ((const float4*)m)[(size_t)row*64 + (c4 - 64)];
    ((float4*)cc)[idx] = v;
}

// ---------------- layernorm + exact gelu (in place, width 512) ----------------
__global__ void ln_gelu_kernel(float* __restrict__ H, const float* __restrict__ g,
                               const float* __restrict__ bb)
{
    int row = blockIdx.x, tid = threadIdx.x;
    float* h = H + (size_t)row * 512;
    float x[4];
    float s = 0.f;
    __shared__ float red[128];
    #pragma unroll
    for (int i = 0; i < 4; i++) { x[i] = h[tid + i*128]; s += x[i]; }
    red[tid] = s; __syncthreads();
    for (int o = 64; o; o >>= 1) { if (tid < o) red[tid] += red[tid+o]; __syncthreads(); }
    float mu = red[0] * (1.f/512.f); __syncthreads();
    float s2 = 0.f;
    #pragma unroll
    for (int i = 0; i < 4; i++) { float d = x[i] - mu; s2 += d*d; }
    red[tid] = s2; __syncthreads();
    for (int o = 64; o; o >>= 1) { if (tid < o) red[tid] += red[tid+o]; __syncthreads(); }
    float rstd = rsqrtf(red[0] * (1.f/512.f) + LN_EPS);
    #pragma unroll
    for (int i = 0; i < 4; i++) {
        int c = tid + i*128;
        float y = (x[i] - mu) * rstd * g[c] + bb[c];
        h[c] = y * 0.5f * (1.f + erff(y * 0.70710678118654752f));
    }
}

// ---------------- z = d @ Wz + bz ----------------
__global__ void zdot_kernel(const float* __restrict__ Dm, const float* __restrict__ Wz,
                            const float* __restrict__ bz, float* __restrict__ z, int rows)
{
    int warp = (blockIdx.x * blockDim.x + threadIdx.x) >> 5;
    int lane = threadIdx.x & 31;
    if (warp >= rows) return;
    const float* r = Dm + (size_t)warp * DD;
    float s = 0.f;
    for (int k = lane; k < DD; k += 32) s += r[k] * Wz[k];
    for (int o = 16; o; o >>= 1) s += __shfl_down_sync(0xffffffffu, s, o);
    if (lane == 0) z[warp] = s + bz[0];
}

// ---------------- prep: radj/cadj/borders ----------------
__global__ void prep_kernel(const float* __restrict__ z0, const float* __restrict__ z1,
                            const float* __restrict__ rlse, const float* __restrict__ clse,
                            float* __restrict__ radj, float* __restrict__ cadj,
                            float* __restrict__ brd0, float* __restrict__ brd1)
{
    int idx = blockIdx.x * blockDim.x + threadIdx.x;
    if (idx >= 8192) return;
    float a = z0[idx], b = z1[idx];
    radj[idx] = -softplusf(-a) - rlse[idx];
    cadj[idx] = -softplusf(-b) - clse[idx];
    brd0[idx] = -softplusf(a);
    brd1[idx] = -softplusf(b);
}

// ---------------- scores assembly ----------------
__global__ void assemble_kernel(const float* __restrict__ sim,
                                const float* __restrict__ radj, const float* __restrict__ cadj,
                                const float* __restrict__ brd0, const float* __restrict__ brd1,
                                float* __restrict__ out)
{
    int b = blockIdx.y, i = blockIdx.x;
    float* o = out + (size_t)b * 2049 * 2049 + (size_t)i * 2049;
    if (i < MM) {
        const float* sr = sim + (size_t)b*MM*NN + (size_t)i*NN;
        float ra = radj[b*MM + i];
        for (int j = threadIdx.x; j < NN; j += blockDim.x)
            o[j] = 2.f * sr[j] + ra + cadj[b*NN + j];
        if (threadIdx.x == 0) o[NN] = brd0[b*MM + i];
    } else {
        for (int j = threadIdx.x; j < NN; j += blockDim.x)
            o[j] = brd1[b*NN + j];
        if (threadIdx.x == 0) o[NN] = 0.f;
    }
}

// ---------------- row / col argmax over inner ----------------
__global__ void row_argmax_kernel(const float* __restrict__ sim,
                                  const float* __restrict__ radj, const float* __restrict__ cadj,
                                  float* __restrict__ rowv, int* __restrict__ rowj)
{
    int b = blockIdx.y, i = blockIdx.x, tid = threadIdx.x;
    const float* sr = sim + (size_t)b*MM*NN + (size_t)i*NN;
    float best = NEG_HUGE; int bj = 0;
    for (int j = tid; j < NN; j += 256) {
        float v = 2.f * sr[j] + cadj[b*NN + j];
        if (v > best) { best = v; bj = j; }
    }
    __shared__ float sv[256]; __shared__ int sj[256];
    sv[tid] = best; sj[tid] = bj; __syncthreads();
    for (int o = 128; o; o >>= 1) {
        if (tid < o) {
            float v2 = sv[tid+o]; int j2 = sj[tid+o];
            if (v2 > sv[tid] || (v2 == sv[tid] && j2 < sj[tid])) { sv[tid] = v2; sj[tid] = j2; }
        }
        __syncthreads();
    }
    if (tid == 0) { rowv[b*MM + i] = sv[0] + radj[b*MM + i]; rowj[b*MM + i] = sj[0]; }
}

__global__ void col_argmax_kernel(const float* __restrict__ sim,
                                  const float* __restrict__ radj, const float* __restrict__ cadj,
                                  float* __restrict__ colv, int* __restrict__ colj)
{
    int b = blockIdx.y, tid = threadIdx.x;
    int col = blockIdx.x * 32 + (tid & 31);
    int part = tid >> 5;
    const float* Sb = sim + (size_t)b*MM*NN;
    float best = NEG_HUGE; int bi = 0;
    for (int i = part; i < MM; i += 8) {
        float v = 2.f * Sb[(size_t)i*NN + col] + radj[b*MM + i];
        if (v > best) { best = v; bi = i; }
    }
    __shared__ float sv[256]; __shared__ int si[256];
    sv[tid] = best; si[tid] = bi; __syncthreads();
    if (part == 0) {
        for (int p = 1; p < 8; p++) {
            float v2 = sv[p*32 + tid]; int i2 = si[p*32 + tid];
            if (v2 > best || (v2 == best && i2 < bi)) { best = v2; bi = i2; }
        }
        colv[b*NN + col] = best + cadj[b*NN + col];
        colj[b*NN + col] = bi;
    }
}

// ---------------- mutual-match filter ----------------
__global__ void filter0_kernel(const int* __restrict__ rowj, const int* __restrict__ colj,
                               const float* __restrict__ rowv,
                               float* __restrict__ ms0_s, int* __restrict__ valid0,
                               float* __restrict__ out_m0, float* __restrict__ out_ms0)
{
    int idx = blockIdx.x * blockDim.x + threadIdx.x;
    if (idx >= 8192) return;
    int b = idx / MM, i = idx % MM;
    int i0 = rowj[idx];
    bool mut = (colj[b*NN + i0] == i);
    float ms0 = mut ? expf(rowv[idx]) : 0.f;
    bool valid = mut && (ms0 > TH_VAL);
    ms0_s[idx] = ms0;
    valid0[idx] = valid ? 1 : 0;
    out_m0[idx] = valid ? (float)i0 : -1.f;
    out_ms0[idx] = ms0;
}

__global__ void filter1_kernel(const int* __restrict__ rowj, const int* __restrict__ colj,
                               const float* __restrict__ ms0_s, const int* __restrict__ valid0,
                               float* __restrict__ out_m1, float* __restrict__ out_ms1)
{
    int idx = blockIdx.x * blockDim.x + threadIdx.x;
    if (idx >= 8192) return;
    int b = idx / NN, j = idx % NN;
    int i1 = colj[idx];
    bool mut = (rowj[b*MM + i1] == j);
    float ms1 = mut ? ms0_s[b*MM + i1] : 0.f;
    bool valid = mut && (valid0[b*MM + i1] != 0);
    out_m1[idx] = valid ? (float)i1 : -1.f;
    out_ms1[idx] = ms1;
}

// ---------------- host launchers ----------------
static inline void launch_gemm_tn(const float* A, const float* Bt, const float* bias,
                                  const float* res, float scale, float* C,
                                  int R, int N, int K, int batch,
                                  long sA, long sB, long sC, long sRes)
{
    dim3 g(N / GBN, R / GBM, batch);
    gemm_tn_kernel<<<g, 256>>>(A, Bt, bias, res, scale, C, R, N, K, sA, sB, sC, sRes);
}

static inline void launch_gemm_nn(const float* A, const float* Bmat, const float* bias,
                                  float* C, int R, int N, int K, int batch,
                                  long sA, long sB, long sC)
{
    dim3 g(N / GBN, R / GBM, batch);
    gemm_nn_kernel<<<g, 256>>>(A, Bmat, bias, C, R, N, K, sA, sB, sC);
}

extern "C" void kernel_launch(void* const* d_in, const int* in_sizes, int n_in,
                              void* d_out, int out_size)
{
    const float* x0  = (const float*)d_in[0];
    const float* x1  = (const float*)d_in[1];
    const float* adj = (const float*)d_in[2];
    const float* Wv  = (const float*)d_in[3];
    const float* bv  = (const float*)d_in[4];
    const float* Wo  = (const float*)d_in[5];
    const float* bo  = (const float*)d_in[6];
    const float* Wf1 = (const float*)d_in[7];
    const float* bf1 = (const float*)d_in[8];
    const float* lng = (const float*)d_in[9];
    const float* lnb = (const float*)d_in[10];
    const float* Wf2 = (const float*)d_in[11];
    const float* bf2 = (const float*)d_in[12];
    const float* Wfp = (const float*)d_in[13];
    const float* bfp = (const float*)d_in[14];
    const float* Wz  = (const float*)d_in[15];
    const float* bz  = (const float*)d_in[16];
    float* out = (float*)d_out;

    float* S; cudaGetSymbolAddress((void**)&S, g_scratch);
    int* IS;  cudaGetSymbolAddress((void**)&IS, g_iscratch);

    float *P01 = S + O_P01, *P10 = S + O_P10, *SIM = S + O_SIM;
    float *V0 = S + O_V0, *V1 = S + O_V1, *MP0 = S + O_MP0, *MP1 = S + O_MP1;
    float *M0 = S + O_M0, *M1 = S + O_M1;
    float *CC0 = S + O_CC0, *CC1 = S + O_CC1, *H0 = S + O_H0, *H1 = S + O_H1;
    float *D0 = S + O_D0, *D1 = S + O_D1, *MD0 = S + O_MD0, *MD1 = S + O_MD1;
    float *RMAX = S + O_RMAX, *RINV = S + O_RINV, *CMAX = S + O_CMAX, *CINV = S + O_CINV;
    float *RLSE = S + O_RLSE, *CLSE = S + O_CLSE, *Z0 = S + O_Z0, *Z1 = S + O_Z1;
    float *RADJ = S + O_RADJ, *CADJ = S + O_CADJ, *BRD0 = S + O_BRD0, *BRD1 = S + O_BRD1;
    float *ROWV = S + O_ROWV, *COLV = S + O_COLV, *MS0S = S + O_MS0;
    int *ROWJ = IS, *COLJ = IS + 8192, *VAL0 = IS + 16384;

    const int RALL = BB * MM;   // 8192

    // 1. v = x @ Wv^T + bv
    launch_gemm_tn(x0, Wv, bv, nullptr, 1.f, V0, RALL, DD, DD, 1, 0, 0, 0, 0);
    launch_gemm_tn(x1, Wv, bv, nullptr, 1.f, V1, RALL, DD, DD, 1, 0, 0, 0, 0);

    // 2. adjacency softmax stats
    reduce_rows_kernel<<<dim3(MM, BB), 256>>>(adj, MM, NN, 0, RMAX, RINV);
    reduce_cols_kernel<<<dim3(NN/32, BB), 256>>>(adj, MM, NN, 0, CMAX, CINV);

    // 3. materialize P01 and transposed P10
    build_P_kernel<<<dim3(NN/32, MM/32, BB), dim3(32, 8)>>>(adj, RMAX, RINV, CMAX, CINV, P01, P10);

    // 4. message passing
    launch_gemm_nn(P01, V1, nullptr, MP0, MM, DD, NN, BB,
                   (long)MM*NN, (long)NN*DD, (long)MM*DD);
    launch_gemm_nn(P10, V0, nullptr, MP1, NN, DD, MM, BB,
                   (long)NN*MM, (long)MM*DD, (long)NN*DD);
    launch_gemm_tn(MP0, Wo, bo, nullptr, 1.f, M0, RALL, DD, DD, 1, 0, 0, 0, 0);
    launch_gemm_tn(MP1, Wo, bo, nullptr, 1.f, M1, RALL, DD, DD, 1, 0, 0, 0, 0);

    // 5. FFN
    concat_kernel<<<(RALL*128 + 255)/256, 256>>>(x0, M0, CC0, RALL);
    concat_kernel<<<(RALL*128 + 255)/256, 256>>>(x1, M1, CC1, RALL);
    launch_gemm_tn(CC0, Wf1, bf1, nullptr, 1.f, H0, RALL, D2, D2, 1, 0, 0, 0, 0);
    launch_gemm_tn(CC1, Wf1, bf1, nullptr, 1.f, H1, RALL, D2, D2, 1, 0, 0, 0, 0);
    ln_gelu_kernel<<<RALL, 128>>>(H0, lng, lnb);
    ln_gelu_kernel<<<RALL, 128>>>(H1, lng, lnb);
    launch_gemm_tn(H0, Wf2, bf2, x0, 1.f, D0, RALL, DD, D2, 1, 0, 0, 0, 0);
    launch_gemm_tn(H1, Wf2, bf2, x1, 1.f, D1, RALL, DD, D2, 1, 0, 0, 0, 0);

    // 6. projections + z
    launch_gemm_tn(D0, Wfp, bfp, nullptr, 0.25f, MD0, RALL, DD, DD, 1, 0, 0, 0, 0);
    launch_gemm_tn(D1, Wfp, bfp, nullptr, 0.25f, MD1, RALL, DD, DD, 1, 0, 0, 0, 0);
    zdot_kernel<<<(RALL*32 + 127)/128, 128>>>(D0, Wz, bz, Z0, RALL);
    zdot_kernel<<<(RALL*32 + 127)/128, 128>>>(D1, Wz, bz, Z1, RALL);

    // 7. sim = md0 @ md1^T (batched)
    launch_gemm_tn(MD0, MD1, nullptr, nullptr, 1.f, SIM, MM, NN, DD, BB,
                   (long)MM*DD, (long)NN*DD, (long)MM*NN, 0);

    // 8. log-softmax stats over sim
    reduce_rows_kernel<<<dim3(MM, BB), 256>>>(SIM, MM, NN, 1, RLSE, nullptr);
    reduce_cols_kernel<<<dim3(NN/32, BB), 256>>>(SIM, MM, NN, 1, CLSE, nullptr);

    // 9. adjustments + borders
    prep_kernel<<<32, 256>>>(Z0, Z1, RLSE, CLSE, RADJ, CADJ, BRD0, BRD1);

    // 10. scores -> d_out
    assemble_kernel<<<dim3(2049, BB), 256>>>(SIM, RADJ, CADJ, BRD0, BRD1, out);

    // 11. argmax passes
    row_argmax_kernel<<<dim3(MM, BB), 256>>>(SIM, RADJ, CADJ, ROWV, ROWJ);
    col_argmax_kernel<<<dim3(NN/32, BB), 256>>>(SIM, RADJ, CADJ, COLV, COLJ);

    // 12. mutual filter -> tail of d_out
    size_t OB = 4LL * 2049 * 2049;
    filter0_kernel<<<32, 256>>>(ROWJ, COLJ, ROWV, MS0S, VAL0,
                                out + OB, out + OB + 2*8192);
    filter1_kernel<<<32, 256>>>(ROWJ, COLJ, MS0S, VAL0,
                                out + OB + 8192, out + OB + 3*8192);
}

// round 6
// speedup vs baseline: 1.2674x; 1.2674x over previous
#include <cuda_runtime.h>
#include <math.h>
#include <stdint.h>

// Problem dims
#define BB 4
#define MM 2048
#define NN 2048
#define DD 256
#define D2 512
#define LN_EPS 1e-5f
#define TH_VAL 0.1f
#define NEG_HUGE -3.0e38f

// ---------------- scratch ----------------
#define SZP (4LL*2048*2048)
#define SZV (4LL*2048*256)
#define SZH (4LL*2048*512)
#define SZS (8192LL)
#define SZPART (65536LL)

constexpr size_t O_P01 = 0;
constexpr size_t O_P10 = O_P01 + SZP;
constexpr size_t O_SIM = O_P10 + SZP;
constexpr size_t O_V0  = O_SIM + SZP;
constexpr size_t O_V1  = O_V0 + SZV;
constexpr size_t O_MP0 = O_V1 + SZV;
constexpr size_t O_MP1 = O_MP0 + SZV;
constexpr size_t O_M0  = O_MP1 + SZV;
constexpr size_t O_M1  = O_M0 + SZV;
constexpr size_t O_CC0 = O_M1 + SZV;
constexpr size_t O_CC1 = O_CC0 + SZH;
constexpr size_t O_H0  = O_CC1 + SZH;
constexpr size_t O_H1  = O_H0 + SZH;
constexpr size_t O_D0  = O_H1 + SZH;
constexpr size_t O_D1  = O_D0 + SZV;
constexpr size_t O_MD0 = O_D1 + SZV;
constexpr size_t O_MD1 = O_MD0 + SZV;
constexpr size_t O_RMAX = O_MD1 + SZV;
constexpr size_t O_RINV = O_RMAX + SZS;
constexpr size_t O_CMAX = O_RINV + SZS;
constexpr size_t O_CINV = O_CMAX + SZS;
constexpr size_t O_RLSE = O_CINV + SZS;
constexpr size_t O_CLSE = O_RLSE + SZS;
constexpr size_t O_Z0   = O_CLSE + SZS;
constexpr size_t O_Z1   = O_Z0 + SZS;
constexpr size_t O_RADJ = O_Z1 + SZS;
constexpr size_t O_CADJ = O_RADJ + SZS;
constexpr size_t O_BRD0 = O_CADJ + SZS;
constexpr size_t O_BRD1 = O_BRD0 + SZS;
constexpr size_t O_ROWV = O_BRD1 + SZS;
constexpr size_t O_MS0  = O_ROWV + SZS;
constexpr size_t O_PM   = O_MS0 + SZS;     // partial col max  [B][8][C]
constexpr size_t O_PS   = O_PM + SZPART;   // partial col sum
constexpr size_t O_PAV  = O_PS + SZPART;   // partial col argmax val
constexpr size_t O_TOTAL = O_PAV + SZPART;

__device__ __align__(16) float g_scratch[O_TOTAL];
__device__ int g_iscratch[3 * 8192 + 65536];   // rowj, colj, valid0, partial argmax idx

__device__ __forceinline__ float softplusf(float x) {
    return fmaxf(x, 0.f) + log1pf(expf(-fabsf(x)));
}

// ================= tf32 MMA GEMM =================
// C = scale*(A @ B + bias) + res
// A: [R,K] row-major. B either [N,K] (Bt, K-contig) or [K,N] (n-contig).
// 3xTF32: split inputs into hi/lo tf32, acc += Ah*Bh + Ah*Bl + Al*Bh.

__device__ __forceinline__ void tf32_split(float x, float& h, float& l) {
    uint32_t hb;
    asm("cvt.rna.tf32.f32 %0, %1;" : "=r"(hb) : "f"(x));
    h = __uint_as_float(hb);
    float r = x - h;
    uint32_t lb;
    asm("cvt.rna.tf32.f32 %0, %1;" : "=r"(lb) : "f"(r));
    l = __uint_as_float(lb);
}

__device__ __forceinline__ void mma8(float* c, const uint32_t* a, const uint32_t* b) {
    asm volatile(
        "mma.sync.aligned.m16n8k8.row.col.f32.tf32.tf32.f32 "
        "{%0,%1,%2,%3}, {%4,%5,%6,%7}, {%8,%9}, {%0,%1,%2,%3};\n"
        : "+f"(c[0]), "+f"(c[1]), "+f"(c[2]), "+f"(c[3])
        : "r"(a[0]), "r"(a[1]), "r"(a[2]), "r"(a[3]), "r"(b[0]), "r"(b[1]));
}

#define BMT 128  // M tile

template <int BN, bool B_IS_NK>
__global__ __launch_bounds__(256, 2) void mma_gemm(
    const float* __restrict__ A, const float* __restrict__ Bg,
    const float* __restrict__ bias, const float* __restrict__ res,
    float scale, float* __restrict__ C,
    int R, int N, int K,
    long sA, long sB, long sC, long sRes)
{
    constexpr int WN = BN / 32;        // warps along N (4 or 2)
    constexpr int WM = 8 / WN;         // warps along M (2 or 4)
    constexpr int MROWS = BMT / WM;    // rows per warp (64 or 32)
    constexpr int MFRAG = MROWS / 16;  // m16 frags per warp (4 or 2)
    constexpr int NFRAG = 4;           // 32 cols / 8

    __shared__ float Ah[BMT][20], Al[BMT][20];
    __shared__ float Bh[BN][20],  Bl[BN][20];

    int b = blockIdx.z;
    A += (long)b * sA; Bg += (long)b * sB; C += (long)b * sC;
    if (res) res += (long)b * sRes;

    int bm = blockIdx.y * BMT;
    int bn = blockIdx.x * BN;
    int tid = threadIdx.x;
    int wid = tid >> 5, lane = tid & 31;
    int g = lane >> 2, t4 = lane & 3;
    int wn = wid % WN, wm = wid / WN;

    float acc[MFRAG][NFRAG][4];
    #pragma unroll
    for (int i = 0; i < MFRAG; i++)
        #pragma unroll
        for (int j = 0; j < NFRAG; j++)
            #pragma unroll
            for (int q = 0; q < 4; q++) acc[i][j][q] = 0.f;

    for (int k0 = 0; k0 < K; k0 += 16) {
        // ---- load A tile [BMT x 16] (K-contig) ----
        #pragma unroll
        for (int f = tid; f < BMT * 4; f += 256) {
            int row = f >> 2, k4 = (f & 3) << 2;
            float4 v = *(const float4*)(A + (long)(bm + row) * K + k0 + k4);
            float h0,l0,h1,l1,h2,l2,h3,l3;
            tf32_split(v.x, h0, l0); tf32_split(v.y, h1, l1);
            tf32_split(v.z, h2, l2); tf32_split(v.w, h3, l3);
            *(float4*)&Ah[row][k4] = make_float4(h0, h1, h2, h3);
            *(float4*)&Al[row][k4] = make_float4(l0, l1, l2, l3);
        }
        // ---- load B tile ----
        if (B_IS_NK) {
            #pragma unroll
            for (int f = tid; f < BN * 4; f += 256) {
                int n = f >> 2, k4 = (f & 3) << 2;
                float4 v = *(const float4*)(Bg + (long)(bn + n) * K + k0 + k4);
                float h0,l0,h1,l1,h2,l2,h3,l3;
                tf32_split(v.x, h0, l0); tf32_split(v.y, h1, l1);
                tf32_split(v.z, h2, l2); tf32_split(v.w, h3, l3);
                *(float4*)&Bh[n][k4] = make_float4(h0, h1, h2, h3);
                *(float4*)&Bl[n][k4] = make_float4(l0, l1, l2, l3);
            }
        } else {
            #pragma unroll
            for (int f = tid; f < BN * 4; f += 256) {
                int k = f / (BN / 4);
                int n4 = (f % (BN / 4)) << 2;
                float4 v = *(const float4*)(Bg + (long)(k0 + k) * N + bn + n4);
                float h, l;
                tf32_split(v.x, h, l); Bh[n4+0][k] = h; Bl[n4+0][k] = l;
                tf32_split(v.y, h, l); Bh[n4+1][k] = h; Bl[n4+1][k] = l;
                tf32_split(v.z, h, l); Bh[n4+2][k] = h; Bl[n4+2][k] = l;
                tf32_split(v.w, h, l); Bh[n4+3][k] = h; Bl[n4+3][k] = l;
            }
        }
        __syncthreads();

        #pragma unroll
        for (int kk = 0; kk < 16; kk += 8) {
            uint32_t bh[NFRAG][2], bl[NFRAG][2];
            #pragma unroll
            for (int fn = 0; fn < NFRAG; fn++) {
                int n = wn * 32 + fn * 8 + g;
                bh[fn][0] = __float_as_uint(Bh[n][kk + t4]);
                bh[fn][1] = __float_as_uint(Bh[n][kk + t4 + 4]);
                bl[fn][0] = __float_as_uint(Bl[n][kk + t4]);
                bl[fn][1] = __float_as_uint(Bl[n][kk + t4 + 4]);
            }
            #pragma unroll
            for (int fm = 0; fm < MFRAG; fm++) {
                int m = wm * MROWS + fm * 16 + g;
                uint32_t ah[4], al[4];
                ah[0] = __float_as_uint(Ah[m][kk + t4]);
                ah[1] = __float_as_uint(Ah[m + 8][kk + t4]);
                ah[2] = __float_as_uint(Ah[m][kk + t4 + 4]);
                ah[3] = __float_as_uint(Ah[m + 8][kk + t4 + 4]);
                al[0] = __float_as_uint(Al[m][kk + t4]);
                al[1] = __float_as_uint(Al[m + 8][kk + t4]);
                al[2] = __float_as_uint(Al[m][kk + t4 + 4]);
                al[3] = __float_as_uint(Al[m + 8][kk + t4 + 4]);
                #pragma unroll
                for (int fn = 0; fn < NFRAG; fn++) {
                    mma8(acc[fm][fn], ah, bh[fn]);
                    mma8(acc[fm][fn], ah, bl[fn]);
                    mma8(acc[fm][fn], al, bh[fn]);
                }
            }
        }
        __syncthreads();
    }

    // ---- epilogue ----
    #pragma unroll
    for (int fm = 0; fm < MFRAG; fm++) {
        int row0 = bm + wm * MROWS + fm * 16 + g;
        #pragma unroll
        for (int fn = 0; fn < NFRAG; fn++) {
            int col0 = bn + wn * 32 + fn * 8 + t4 * 2;
            float b0 = bias ? bias[col0] : 0.f;
            float b1 = bias ? bias[col0 + 1] : 0.f;
            float v00 = (acc[fm][fn][0] + b0) * scale;
            float v01 = (acc[fm][fn][1] + b1) * scale;
            float v10 = (acc[fm][fn][2] + b0) * scale;
            float v11 = (acc[fm][fn][3] + b1) * scale;
            if (res) {
                v00 += res[(long)row0 * N + col0];
                v01 += res[(long)row0 * N + col0 + 1];
                v10 += res[(long)(row0 + 8) * N + col0];
                v11 += res[(long)(row0 + 8) * N + col0 + 1];
            }
            *(float2*)&C[(long)row0 * N + col0] = make_float2(v00, v01);
            *(float2*)&C[(long)(row0 + 8) * N + col0] = make_float2(v10, v11);
        }
    }
}

// ================= reductions =================
// Online row reduce. mode 0: out0=max, out1=1/sumexp ; mode 1: out0=lse
__global__ void reduce_rows_kernel(const float* __restrict__ X, int R, int C, int mode,
                                   float* __restrict__ out0, float* __restrict__ out1)
{
    int b = blockIdx.y, row = blockIdx.x, tid = threadIdx.x;
    const float* xr = X + (size_t)(b * R + row) * C;
    float mx = NEG_HUGE, s = 0.f;
    for (int j = tid; j < C; j += 256) {
        float a = xr[j];
        if (a > mx) { s = s * expf(mx - a) + 1.f; mx = a; }
        else s += expf(a - mx);
    }
    __shared__ float smx[256], ssum[256];
    smx[tid] = mx; ssum[tid] = s; __syncthreads();
    for (int o = 128; o; o >>= 1) {
        if (tid < o) {
            float m2 = smx[tid + o], s2 = ssum[tid + o];
            float m1 = smx[tid], s1 = ssum[tid];
            if (m2 > m1) { ssum[tid] = s1 * expf(m1 - m2) + s2; smx[tid] = m2; }
            else ssum[tid] = s1 + s2 * expf(m2 - m1);
        }
        __syncthreads();
    }
    if (tid == 0) {
        int o = b * R + row;
        if (mode == 0) { out0[o] = smx[0]; out1[o] = 1.f / ssum[0]; }
        else out0[o] = smx[0] + logf(ssum[0]);
    }
}

// Two-stage column softmax stats. Stage1: per 256-row chunk partials.
#define RCH 256
__global__ void colred1_kernel(const float* __restrict__ X, int R, int C,
                               float* __restrict__ pmx, float* __restrict__ psum)
{
    int b = blockIdx.z, ch = blockIdx.y;
    int tid = threadIdx.x;
    int col = blockIdx.x * 32 + (tid & 31);
    int part = tid >> 5;
    const float* Xb = X + (size_t)b * R * C;
    int r0 = ch * RCH;
    float mx = NEG_HUGE, s = 0.f;
    for (int i = r0 + part; i < r0 + RCH; i += 8) {
        float a = Xb[(size_t)i * C + col];
        if (a > mx) { s = s * expf(mx - a) + 1.f; mx = a; }
        else s += expf(a - mx);
    }
    __shared__ float smx[256], ssum[256];
    smx[tid] = mx; ssum[tid] = s; __syncthreads();
    if (part == 0) {
        for (int p = 1; p < 8; p++) {
            float m2 = smx[p * 32 + tid], s2 = ssum[p * 32 + tid];
            if (m2 > mx) { s = s * expf(mx - m2) + s2; mx = m2; }
            else s += s2 * expf(m2 - mx);
        }
        size_t o = ((size_t)b * 8 + ch) * C + col;
        pmx[o] = mx; psum[o] = s;
    }
}

__global__ void colred2_kernel(const float* __restrict__ pmx, const float* __restrict__ psum,
                               int C, int mode,
                               float* __restrict__ out0, float* __restrict__ out1)
{
    int idx = blockIdx.x * blockDim.x + threadIdx.x;
    if (idx >= BB * C) return;
    int b = idx / C, col = idx % C;
    size_t base = (size_t)b * 8 * C + col;
    float mx = pmx[base], s = psum[base];
    for (int ch = 1; ch < 8; ch++) {
        float m2 = pmx[base + (size_t)ch * C], s2 = psum[base + (size_t)ch * C];
        if (m2 > mx) { s = s * expf(mx - m2) + s2; mx = m2; }
        else s += s2 * expf(m2 - mx);
    }
    if (mode == 0) { out0[idx] = mx; out1[idx] = 1.f / s; }
    else out0[idx] = mx + logf(s);
}

// Two-stage column argmax of v = 2*sim + radj[i]
__global__ void colamax1_kernel(const float* __restrict__ sim, const float* __restrict__ radj,
                                float* __restrict__ pav, int* __restrict__ pai)
{
    int b = blockIdx.z, ch = blockIdx.y;
    int tid = threadIdx.x;
    int col = blockIdx.x * 32 + (tid & 31);
    int part = tid >> 5;
    const float* Sb = sim + (size_t)b * MM * NN;
    int r0 = ch * RCH;
    float best = NEG_HUGE; int bi = 0;
    for (int i = r0 + part; i < r0 + RCH; i += 8) {
        float v = 2.f * Sb[(size_t)i * NN + col] + radj[b * MM + i];
        if (v > best) { best = v; bi = i; }
    }
    __shared__ float sv[256]; __shared__ int si[256];
    sv[tid] = best; si[tid] = bi; __syncthreads();
    if (part == 0) {
        for (int p = 1; p < 8; p++) {
            float v2 = sv[p * 32 + tid]; int i2 = si[p * 32 + tid];
            if (v2 > best || (v2 == best && i2 < bi)) { best = v2; bi = i2; }
        }
        size_t o = ((size_t)b * 8 + ch) * NN + col;
        pav[o] = best; pai[o] = bi;
    }
}

__global__ void colamax2_kernel(const float* __restrict__ pav, const int* __restrict__ pai,
                                int* __restrict__ colj)
{
    int idx = blockIdx.x * blockDim.x + threadIdx.x;
    if (idx >= BB * NN) return;
    int b = idx / NN, col = idx % NN;
    size_t base = (size_t)b * 8 * NN + col;
    float best = pav[base]; int bi = pai[base];
    for (int ch = 1; ch < 8; ch++) {
        float v2 = pav[base + (size_t)ch * NN];
        if (v2 > best) { best = v2; bi = pai[base + (size_t)ch * NN]; }
    }
    colj[idx] = bi;
}

// ---------------- softmax materialization ----------------
__global__ void build_P_kernel(const float* __restrict__ adj,
                               const float* __restrict__ rmax, const float* __restrict__ rinv,
                               const float* __restrict__ cmax, const float* __restrict__ cinv,
                               float* __restrict__ P01, float* __restrict__ P10t)
{
    int b = blockIdx.z;
    int tm = blockIdx.y * 32, tn = blockIdx.x * 32;
    __shared__ float s[32][33];
    const float* A = adj + (size_t)b * MM * NN;
    int tx = threadIdx.x, ty = threadIdx.y;
    #pragma unroll
    for (int i = 0; i < 4; i++) {
        int m = tm + ty + i * 8;
        float a = A[(size_t)m * NN + tn + tx];
        s[ty + i * 8][tx] = a;
        P01[(size_t)b * MM * NN + (size_t)m * NN + tn + tx] =
            expf(a - rmax[b * MM + m]) * rinv[b * MM + m];
    }
    __syncthreads();
    #pragma unroll
    for (int i = 0; i < 4; i++) {
        int n = tn + ty + i * 8;
        int m = tm + tx;
        float a = s[tx][ty + i * 8];
        P10t[(size_t)b * NN * MM + (size_t)n * MM + m] =
            expf(a - cmax[b * NN + n]) * cinv[b * NN + n];
    }
}

// ---------------- concat ----------------
__global__ void concat_kernel(const float* __restrict__ x, const float* __restrict__ m,
                              float* __restrict__ cc, int rows)
{
    int idx = blockIdx.x * blockDim.x + threadIdx.x;
    if (idx >= rows * 128) return;
    int row = idx >> 7, c4 = idx & 127;
    float4 v;
    if (c4 < 64) v = ((const float4*)x)[(size_t)row * 64 + c4];
    else         v = ((const float4*)m)[(size_t)row * 64 + (c4 - 64)];
    ((float4*)cc)[idx] = v;
}

// ---------------- layernorm + exact gelu ----------------
__global__ void ln_gelu_kernel(float* __restrict__ H, const float* __restrict__ g,
                               const float* __restrict__ bb)
{
    int row = blockIdx.x, tid = threadIdx.x;
    float* h = H + (size_t)row * 512;
    float x[4];
    float s = 0.f;
    __shared__ float red[128];
    #pragma unroll
    for (int i = 0; i < 4; i++) { x[i] = h[tid + i * 128]; s += x[i]; }
    red[tid] = s; __syncthreads();
    for (int o = 64; o; o >>= 1) { if (tid < o) red[tid] += red[tid + o]; __syncthreads(); }
    float mu = red[0] * (1.f / 512.f); __syncthreads();
    float s2 = 0.f;
    #pragma unroll
    for (int i = 0; i < 4; i++) { float d = x[i] - mu; s2 += d * d; }
    red[tid] = s2; __syncthreads();
    for (int o = 64; o; o >>= 1) { if (tid < o) red[tid] += red[tid + o]; __syncthreads(); }
    float rstd = rsqrtf(red[0] * (1.f / 512.f) + LN_EPS);
    #pragma unroll
    for (int i = 0; i < 4; i++) {
        int c = tid + i * 128;
        float y = (x[i] - mu) * rstd * g[c] + bb[c];
        h[c] = y * 0.5f * (1.f + erff(y * 0.70710678118654752f));
    }
}

// ---------------- z = d @ Wz + bz ----------------
__global__ void zdot_kernel(const float* __restrict__ Dm, const float* __restrict__ Wz,
                            const float* __restrict__ bz, float* __restrict__ z, int rows)
{
    int warp = (blockIdx.x * blockDim.x + threadIdx.x) >> 5;
    int lane = threadIdx.x & 31;
    if (warp >= rows) return;
    const float* r = Dm + (size_t)warp * DD;
    float s = 0.f;
    for (int k = lane; k < DD; k += 32) s += r[k] * Wz[k];
    for (int o = 16; o; o >>= 1) s += __shfl_down_sync(0xffffffffu, s, o);
    if (lane == 0) z[warp] = s + bz[0];
}

// ---------------- prep ----------------
__global__ void prep_kernel(const float* __restrict__ z0, const float* __restrict__ z1,
                            const float* __restrict__ rlse, const float* __restrict__ clse,
                            float* __restrict__ radj, float* __restrict__ cadj,
                            float* __restrict__ brd0, float* __restrict__ brd1)
{
    int idx = blockIdx.x * blockDim.x + threadIdx.x;
    if (idx >= 8192) return;
    float a = z0[idx], b = z1[idx];
    radj[idx] = -softplusf(-a) - rlse[idx];
    cadj[idx] = -softplusf(-b) - clse[idx];
    brd0[idx] = -softplusf(a);
    brd1[idx] = -softplusf(b);
}

// ---------------- scores assembly + fused row argmax ----------------
__global__ void assemble_kernel(const float* __restrict__ sim,
                                const float* __restrict__ radj, const float* __restrict__ cadj,
                                const float* __restrict__ brd0, const float* __restrict__ brd1,
                                float* __restrict__ out,
                                float* __restrict__ rowv, int* __restrict__ rowj)
{
    int b = blockIdx.y, i = blockIdx.x, tid = threadIdx.x;
    float* o = out + (size_t)b * 2049 * 2049 + (size_t)i * 2049;
    if (i < MM) {
        const float* sr = sim + (size_t)b * MM * NN + (size_t)i * NN;
        float ra = radj[b * MM + i];
        float best = NEG_HUGE; int bj = 0;
        for (int j = tid; j < NN; j += 256) {
            float v = 2.f * sr[j] + cadj[b * NN + j];
            o[j] = v + ra;
            if (v > best) { best = v; bj = j; }
        }
        __shared__ float sv[256]; __shared__ int sj[256];
        sv[tid] = best; sj[tid] = bj; __syncthreads();
        for (int off = 128; off; off >>= 1) {
            if (tid < off) {
                float v2 = sv[tid + off]; int j2 = sj[tid + off];
                if (v2 > sv[tid] || (v2 == sv[tid] && j2 < sj[tid])) { sv[tid] = v2; sj[tid] = j2; }
            }
            __syncthreads();
        }
        if (tid == 0) {
            o[NN] = brd0[b * MM + i];
            rowv[b * MM + i] = sv[0] + ra;
            rowj[b * MM + i] = sj[0];
        }
    } else {
        for (int j = tid; j < NN; j += 256)
            o[j] = brd1[b * NN + j];
        if (tid == 0) o[NN] = 0.f;
    }
}

// ---------------- mutual-match filter ----------------
__global__ void filter0_kernel(const int* __restrict__ rowj, const int* __restrict__ colj,
                               const float* __restrict__ rowv,
                               float* __restrict__ ms0_s, int* __restrict__ valid0,
                               float* __restrict__ out_m0, float* __restrict__ out_ms0)
{
    int idx = blockIdx.x * blockDim.x + threadIdx.x;
    if (idx >= 8192) return;
    int b = idx / MM, i = idx % MM;
    int i0 = rowj[idx];
    bool mut = (colj[b * NN + i0] == i);
    float ms0 = mut ? expf(rowv[idx]) : 0.f;
    bool valid = mut && (ms0 > TH_VAL);
    ms0_s[idx] = ms0;
    valid0[idx] = valid ? 1 : 0;
    out_m0[idx] = valid ? (float)i0 : -1.f;
    out_ms0[idx] = ms0;
}

__global__ void filter1_kernel(const int* __restrict__ rowj, const int* __restrict__ colj,
                               const float* __restrict__ ms0_s, const int* __restrict__ valid0,
                               float* __restrict__ out_m1, float* __restrict__ out_ms1)
{
    int idx = blockIdx.x * blockDim.x + threadIdx.x;
    if (idx >= 8192) return;
    int b = idx / NN, j = idx % NN;
    int i1 = colj[idx];
    bool mut = (rowj[b * MM + i1] == j);
    float ms1 = mut ? ms0_s[b * MM + i1] : 0.f;
    bool valid = mut && (valid0[b * MM + i1] != 0);
    out_m1[idx] = valid ? (float)i1 : -1.f;
    out_ms1[idx] = ms1;
}

// ---------------- host launchers ----------------
static inline void gemm_tn64(const float* A, const float* Bt, const float* bias,
                             const float* res, float scale, float* C,
                             int R, int N, int K, int batch,
                             long sA, long sB, long sC, long sRes)
{
    dim3 g(N / 64, R / BMT, batch);
    mma_gemm<64, true><<<g, 256>>>(A, Bt, bias, res, scale, C, R, N, K, sA, sB, sC, sRes);
}

static inline void gemm_tn128(const float* A, const float* Bt, const float* bias,
                              const float* res, float scale, float* C,
                              int R, int N, int K, int batch,
                              long sA, long sB, long sC, long sRes)
{
    dim3 g(N / 128, R / BMT, batch);
    mma_gemm<128, true><<<g, 256>>>(A, Bt, bias, res, scale, C, R, N, K, sA, sB, sC, sRes);
}

static inline void gemm_nn64(const float* A, const float* Bmat, float* C,
                             int R, int N, int K, int batch,
                             long sA, long sB, long sC)
{
    dim3 g(N / 64, R / BMT, batch);
    mma_gemm<64, false><<<g, 256>>>(A, Bmat, nullptr, nullptr, 1.f, C, R, N, K, sA, sB, sC, 0);
}

extern "C" void kernel_launch(void* const* d_in, const int* in_sizes, int n_in,
                              void* d_out, int out_size)
{
    const float* x0  = (const float*)d_in[0];
    const float* x1  = (const float*)d_in[1];
    const float* adj = (const float*)d_in[2];
    const float* Wv  = (const float*)d_in[3];
    const float* bv  = (const float*)d_in[4];
    const float* Wo  = (const float*)d_in[5];
    const float* bo  = (const float*)d_in[6];
    const float* Wf1 = (const float*)d_in[7];
    const float* bf1 = (const float*)d_in[8];
    const float* lng = (const float*)d_in[9];
    const float* lnb = (const float*)d_in[10];
    const float* Wf2 = (const float*)d_in[11];
    const float* bf2 = (const float*)d_in[12];
    const float* Wfp = (const float*)d_in[13];
    const float* bfp = (const float*)d_in[14];
    const float* Wz  = (const float*)d_in[15];
    const float* bz  = (const float*)d_in[16];
    float* out = (float*)d_out;

    float* S; cudaGetSymbolAddress((void**)&S, g_scratch);
    int* IS;  cudaGetSymbolAddress((void**)&IS, g_iscratch);

    float *P01 = S + O_P01, *P10 = S + O_P10, *SIM = S + O_SIM;
    float *V0 = S + O_V0, *V1 = S + O_V1, *MP0 = S + O_MP0, *MP1 = S + O_MP1;
    float *M0 = S + O_M0, *M1 = S + O_M1;
    float *CC0 = S + O_CC0, *CC1 = S + O_CC1, *H0 = S + O_H0, *H1 = S + O_H1;
    float *D0 = S + O_D0, *D1 = S + O_D1, *MD0 = S + O_MD0, *MD1 = S + O_MD1;
    float *RMAX = S + O_RMAX, *RINV = S + O_RINV, *CMAX = S + O_CMAX, *CINV = S + O_CINV;
    float *RLSE = S + O_RLSE, *CLSE = S + O_CLSE, *Z0 = S + O_Z0, *Z1 = S + O_Z1;
    float *RADJ = S + O_RADJ, *CADJ = S + O_CADJ, *BRD0 = S + O_BRD0, *BRD1 = S + O_BRD1;
    float *ROWV = S + O_ROWV, *MS0S = S + O_MS0;
    float *PM = S + O_PM, *PS = S + O_PS, *PAV = S + O_PAV;
    int *ROWJ = IS, *COLJ = IS + 8192, *VAL0 = IS + 16384, *PAI = IS + 24576;

    const int RALL = BB * MM;   // 8192

    // 1. v = x @ Wv^T + bv
    gemm_tn64(x0, Wv, bv, nullptr, 1.f, V0, RALL, DD, DD, 1, 0, 0, 0, 0);
    gemm_tn64(x1, Wv, bv, nullptr, 1.f, V1, RALL, DD, DD, 1, 0, 0, 0, 0);

    // 2. adjacency softmax stats
    reduce_rows_kernel<<<dim3(MM, BB), 256>>>(adj, MM, NN, 0, RMAX, RINV);
    colred1_kernel<<<dim3(NN / 32, 8, BB), 256>>>(adj, MM, NN, PM, PS);
    colred2_kernel<<<32, 256>>>(PM, PS, NN, 0, CMAX, CINV);

    // 3. materialize P01 and transposed P10
    build_P_kernel<<<dim3(NN / 32, MM / 32, BB), dim3(32, 8)>>>(adj, RMAX, RINV, CMAX, CINV, P01, P10);

    // 4. message passing
    gemm_nn64(P01, V1, MP0, MM, DD, NN, BB, (long)MM * NN, (long)NN * DD, (long)MM * DD);
    gemm_nn64(P10, V0, MP1, NN, DD, MM, BB, (long)NN * MM, (long)MM * DD, (long)NN * DD);
    gemm_tn64(MP0, Wo, bo, nullptr, 1.f, M0, RALL, DD, DD, 1, 0, 0, 0, 0);
    gemm_tn64(MP1, Wo, bo, nullptr, 1.f, M1, RALL, DD, DD, 1, 0, 0, 0, 0);

    // 5. FFN
    concat_kernel<<<(RALL * 128 + 255) / 256, 256>>>(x0, M0, CC0, RALL);
    concat_kernel<<<(RALL * 128 + 255) / 256, 256>>>(x1, M1, CC1, RALL);
    gemm_tn64(CC0, Wf1, bf1, nullptr, 1.f, H0, RALL, D2, D2, 1, 0, 0, 0, 0);
    gemm_tn64(CC1, Wf1, bf1, nullptr, 1.f, H1, RALL, D2, D2, 1, 0, 0, 0, 0);
    ln_gelu_kernel<<<RALL, 128>>>(H0, lng, lnb);
    ln_gelu_kernel<<<RALL, 128>>>(H1, lng, lnb);
    gemm_tn64(H0, Wf2, bf2, x0, 1.f, D0, RALL, DD, D2, 1, 0, 0, 0, 0);
    gemm_tn64(H1, Wf2, bf2, x1, 1.f, D1, RALL, DD, D2, 1, 0, 0, 0, 0);

    // 6. projections + z
    gemm_tn64(D0, Wfp, bfp, nullptr, 0.25f, MD0, RALL, DD, DD, 1, 0, 0, 0, 0);
    gemm_tn64(D1, Wfp, bfp, nullptr, 0.25f, MD1, RALL, DD, DD, 1, 0, 0, 0, 0);
    zdot_kernel<<<(RALL * 32 + 127) / 128, 128>>>(D0, Wz, bz, Z0, RALL);
    zdot_kernel<<<(RALL * 32 + 127) / 128, 128>>>(D1, Wz, bz, Z1, RALL);

    // 7. sim = md0 @ md1^T (batched)
    gemm_tn128(MD0, MD1, nullptr, nullptr, 1.f, SIM, MM, NN, DD, BB,
               (long)MM * DD, (long)NN * DD, (long)MM * NN, 0);

    // 8. log-softmax stats over sim
    reduce_rows_kernel<<<dim3(MM, BB), 256>>>(SIM, MM, NN, 1, RLSE, nullptr);
    colred1_kernel<<<dim3(NN / 32, 8, BB), 256>>>(SIM, MM, NN, PM, PS);
    colred2_kernel<<<32, 256>>>(PM, PS, NN, 1, CLSE, nullptr);

    // 9. adjustments + borders
    prep_kernel<<<32, 256>>>(Z0, Z1, RLSE, CLSE, RADJ, CADJ, BRD0, BRD1);

    // 10. scores -> d_out (+ fused row argmax)
    assemble_kernel<<<dim3(2049, BB), 256>>>(SIM, RADJ, CADJ, BRD0, BRD1, out, ROWV, ROWJ);

    // 11. col argmax (two-stage)
    colamax1_kernel<<<dim3(NN / 32, 8, BB), 256>>>(SIM, RADJ, PAV, PAI);
    colamax2_kernel<<<32, 256>>>(PAV, PAI, COLJ);

    // 12. mutual filter -> tail of d_out
    size_t OB = 4LL * 2049 * 2049;
    filter0_kernel<<<32, 256>>>(ROWJ, COLJ, ROWV, MS0S, VAL0,
                                out + OB, out + OB + 2 * 8192);
    filter1_kernel<<<32, 256>>>(ROWJ, COLJ, MS0S, VAL0,
                                out + OB + 8192, out + OB + 3 * 8192);
}